// round 14
// baseline (speedup 1.0000x reference)
#include <cuda_runtime.h>
#include <cuda_bf16.h>
#include <cstdint>

#define N_NODES 8192
#define F_DIM   256
#define E_EDGES 262144
#define ADJ_ROW_WORDS (N_NODES / 32)              // 256
#define ADJ_WORDS     (N_NODES * ADJ_ROW_WORDS)   // 8MB
#define PB_B_OFF 32768
#define PB_TOTAL 65536
#define COV_SPLITS 16

// penalty: 256x128 tiles, upper-tri (cb >= 2*rb): 1056 tiles
#define PN_TILES 1056
#define PN_STAGE 98304                            // 64KB A + 32KB B
#define PN_B_OFF 65536
#define PN_TOTAL (2 * PN_STAGE)                   // 192KB

// ---------------- scratch ---------------------------------------------------
__device__ int           g_ei[2 * E_EDGES];
__device__ float         g_mean[F_DIM];                // raw column sums
__device__ float         g_covp[COV_SPLITS][F_DIM * F_DIM];  // split-K partials
__device__ __nv_bfloat16 g_corb[F_DIM * F_DIM];
__device__ __nv_bfloat16 g_zmt[F_DIM * N_NODES];       // zm^T bf16
__device__ __nv_bfloat16 g_wzmb[N_NODES * F_DIM];      // w*zm bf16
__device__ __nv_bfloat16 g_zb[N_NODES * F_DIM];        // z2 bf16
__device__ float         g_nrm[N_NODES];
__device__ unsigned      g_adj[ADJ_WORDS];
__device__ float         g_scores[N_NODES];
__device__ float         g_deg[N_NODES];
__device__ double        g_penalty;

__device__ __forceinline__ uint32_t smem_u32(const void* p) {
    uint32_t a;
    asm("{ .reg .u64 t; cvta.to.shared.u64 t, %1; cvt.u32.u64 %0, t; }"
        : "=r"(a) : "l"(p));
    return a;
}
__device__ __forceinline__ void cpa16(uint32_t saddr, const void* g) {
    asm volatile("cp.async.cg.shared.global [%0], [%1], 16;"
                 :: "r"(saddr), "l"(g));
}

// ---- HMMA inner loop for 128x128 tiles (cov / z2) ---------------------------
__device__ __forceinline__ void mma_tile_128(uint32_t sb, int wm, int wn,
                                             int lane, float acc[4][4][4]) {
#pragma unroll
    for (int ks = 0; ks < 128; ks += 16) {
        uint32_t a[4][4];
#pragma unroll
        for (int mt = 0; mt < 4; mt++) {
            int row = wm + mt * 16 + (lane & 15);
            int kc = ks + ((lane >> 4) << 3);
            uint32_t addr = sb + (uint32_t)(row * 256 +
                           ((((kc >> 3)) ^ (row & 7)) << 4));
            asm volatile(
                "ldmatrix.sync.aligned.m8n8.x4.shared.b16 {%0,%1,%2,%3}, [%4];"
                : "=r"(a[mt][0]), "=r"(a[mt][1]), "=r"(a[mt][2]), "=r"(a[mt][3])
                : "r"(addr));
        }
        uint32_t b[4][2];
#pragma unroll
        for (int pr = 0; pr < 2; pr++) {
            int row = wn + pr * 16 + ((lane >> 4) << 3) + (lane & 7);
            int kc = ks + (((lane >> 3) & 1) << 3);
            uint32_t addr = sb + PB_B_OFF + (uint32_t)(row * 256 +
                           ((((kc >> 3)) ^ (row & 7)) << 4));
            asm volatile(
                "ldmatrix.sync.aligned.m8n8.x4.shared.b16 {%0,%1,%2,%3}, [%4];"
                : "=r"(b[pr * 2][0]), "=r"(b[pr * 2][1]),
                  "=r"(b[pr * 2 + 1][0]), "=r"(b[pr * 2 + 1][1])
                : "r"(addr));
        }
#pragma unroll
        for (int mt = 0; mt < 4; mt++)
#pragma unroll
            for (int nt = 0; nt < 4; nt++)
                asm volatile(
                    "mma.sync.aligned.m16n8k16.row.col.f32.bf16.bf16.f32 "
                    "{%0,%1,%2,%3}, {%4,%5,%6,%7}, {%8,%9}, {%0,%1,%2,%3};"
                    : "+f"(acc[mt][nt][0]), "+f"(acc[mt][nt][1]),
                      "+f"(acc[mt][nt][2]), "+f"(acc[mt][nt][3])
                    : "r"(a[mt][0]), "r"(a[mt][1]), "r"(a[mt][2]), "r"(a[mt][3]),
                      "r"(b[nt][0]), "r"(b[nt][1]));
    }
}

// ---- HMMA inner loop for 256x128 tiles (penalty): warps 4(m) x 2(n) --------
__device__ __forceinline__ void mma_tile_256(uint32_t sbA, uint32_t sbB,
                                             int wm, int wn, int lane,
                                             float acc[4][8][4]) {
#pragma unroll
    for (int ks = 0; ks < 128; ks += 16) {
        uint32_t a[4][4];
#pragma unroll
        for (int mt = 0; mt < 4; mt++) {
            int row = wm + mt * 16 + (lane & 15);
            int kc = ks + ((lane >> 4) << 3);
            uint32_t addr = sbA + (uint32_t)(row * 256 +
                           ((((kc >> 3)) ^ (row & 7)) << 4));
            asm volatile(
                "ldmatrix.sync.aligned.m8n8.x4.shared.b16 {%0,%1,%2,%3}, [%4];"
                : "=r"(a[mt][0]), "=r"(a[mt][1]), "=r"(a[mt][2]), "=r"(a[mt][3])
                : "r"(addr));
        }
        uint32_t b[8][2];
#pragma unroll
        for (int pr = 0; pr < 4; pr++) {
            int row = wn + pr * 16 + ((lane >> 4) << 3) + (lane & 7);
            int kc = ks + (((lane >> 3) & 1) << 3);
            uint32_t addr = sbB + (uint32_t)(row * 256 +
                           ((((kc >> 3)) ^ (row & 7)) << 4));
            asm volatile(
                "ldmatrix.sync.aligned.m8n8.x4.shared.b16 {%0,%1,%2,%3}, [%4];"
                : "=r"(b[pr * 2][0]), "=r"(b[pr * 2][1]),
                  "=r"(b[pr * 2 + 1][0]), "=r"(b[pr * 2 + 1][1])
                : "r"(addr));
        }
#pragma unroll
        for (int mt = 0; mt < 4; mt++)
#pragma unroll
            for (int nt = 0; nt < 8; nt++)
                asm volatile(
                    "mma.sync.aligned.m16n8k16.row.col.f32.bf16.bf16.f32 "
                    "{%0,%1,%2,%3}, {%4,%5,%6,%7}, {%8,%9}, {%0,%1,%2,%3};"
                    : "+f"(acc[mt][nt][0]), "+f"(acc[mt][nt][1]),
                      "+f"(acc[mt][nt][2]), "+f"(acc[mt][nt][3])
                    : "r"(a[mt][0]), "r"(a[mt][1]), "r"(a[mt][2]), "r"(a[mt][3]),
                      "r"(b[nt][0]), "r"(b[nt][1]));
    }
}

// ---------------- zero scratch ----------------------------------------------
__global__ void zero_kernel() {
    int i = blockIdx.x * blockDim.x + threadIdx.x;
    int stride = gridDim.x * blockDim.x;
    for (int idx = i; idx < ADJ_WORDS; idx += stride) g_adj[idx] = 0u;
    if (i < F_DIM) g_mean[i] = 0.f;
    if (i < N_NODES) { g_scores[i] = 0.f; g_deg[i] = 0.f; }
    if (i == 0) g_penalty = 0.0;
}

// ---- grid-union: blocks 0-255 column sums; blocks 256-1279 edges+adjacency -
__global__ void mean_conv_kernel(const float* __restrict__ z,
                                 const void* __restrict__ ei_raw) {
    if (blockIdx.x < 256) {
        int f = threadIdx.x;
        int r0 = blockIdx.x * 32;
        float acc = 0.f;
        for (int r = 0; r < 32; r++) acc += z[(r0 + r) * F_DIM + f];
        atomicAdd(&g_mean[f], acc);
        return;
    }
    const long long* p = (const long long*)ei_raw;
    int bad = 0;
    if (threadIdx.x < 128) {
        long long v = p[threadIdx.x];
        bad = (v < 0 || v >= N_NODES) ? 1 : 0;
    }
    bad = __syncthreads_or(bad);               // 1 => data is int32
    int e = (blockIdx.x - 256) * blockDim.x + threadIdx.x;
    if (e >= E_EDGES) return;
    int i, j;
    if (bad) {
        i = ((const int*)ei_raw)[e];
        j = ((const int*)ei_raw)[E_EDGES + e];
    } else {
        i = (int)p[e];
        j = (int)p[E_EDGES + e];
    }
    i = min(max(i, 0), N_NODES - 1);
    j = min(max(j, 0), N_NODES - 1);
    g_ei[e] = i;
    g_ei[E_EDGES + e] = j;
    atomicOr(&g_adj[i * ADJ_ROW_WORDS + (j >> 5)], 1u << (j & 31));
    atomicOr(&g_adj[j * ADJ_ROW_WORDS + (i >> 5)], 1u << (i & 31));
}

// ---- build zm^T bf16 and w*zm bf16 (w + mean scaling folded in) ------------
__global__ void prep2_kernel(const float* __restrict__ z,
                             const void* __restrict__ ei_raw,
                             const void* __restrict__ k2u_raw,
                             const void* __restrict__ u2k_raw) {
    __shared__ __nv_bfloat16 S[64][258];
    __shared__ float Wv[64];
    __shared__ float Mv[256];
    int n0 = blockIdx.x * 64;
    int t = threadIdx.x;

    // dtype probe (per block, cheap: 128 L2-hit loads)
    const long long* p = (const long long*)ei_raw;
    int bad = 0;
    if (t < 128) {
        long long v = p[t];
        bad = (v < 0 || v >= N_NODES) ? 1 : 0;
    }
    bad = __syncthreads_or(bad);

    if (t < 64) {
        int n = n0 + t;
        float fa, fb;
        if (bad) {
            fa = (float)((const int*)k2u_raw)[n];
            fb = (float)((const int*)u2k_raw)[n];
        } else {
            fa = (float)((const long long*)k2u_raw)[n];
            fb = (float)((const long long*)u2k_raw)[n];
        }
        Wv[t] = __powf(0.9f, fa) + 1.f - __powf(0.9f, fb);
    }
    Mv[t] = g_mean[t] * (1.f / (float)N_NODES);
    __syncthreads();

    for (int idx = t; idx < 64 * 256; idx += 256) {
        int nl = idx >> 8, f = idx & 255;
        float zm = z[(n0 + nl) * F_DIM + f] - Mv[f];
        S[nl][f] = __float2bfloat16(zm);
        g_wzmb[(n0 + nl) * F_DIM + f] = __float2bfloat16(Wv[nl] * zm);
    }
    __syncthreads();
    for (int idx = t; idx < 256 * 64; idx += 256) {
        int f = idx >> 6, nl = idx & 63;
        g_zmt[f * N_NODES + n0 + nl] = S[nl][f];
    }
}

// ---- cov via HMMA: 3 symmetric tiles x 16 K-splits, atomic-free partials ---
__global__ void __launch_bounds__(256) cov_mma_kernel() {
    extern __shared__ char smem[];
    uint32_t sb = smem_u32(smem);
    int t = threadIdx.x, wid = t >> 5, lane = t & 31;
    int tid = blockIdx.x;                    // 0:(0,0) 1:(0,1) 2:(1,1)
    int sp  = blockIdx.y;                    // split index
    int fb1 = (tid == 2) ? 1 : 0;
    int fb2 = (tid == 0) ? 0 : 1;
    int r0 = fb1 * 128, c0 = fb2 * 128;
    int k0 = sp * (N_NODES / COV_SPLITS);    // 512 per split

    int wm = (wid >> 2) * 64, wn = (wid & 3) * 32;
    float acc[4][4][4] = {};

    for (int ph = 0; ph < 4; ph++) {
        if (ph) __syncthreads();
        for (int q = t; q < 2048; q += 256) {
            int row = q >> 4, unit = q & 15;
            uint32_t off = (uint32_t)(row * 256 + ((unit ^ (row & 7)) << 4));
            *(uint4*)(smem + off) =
                *(const uint4*)(g_zmt + (r0 + row) * N_NODES + k0 + ph * 128 + unit * 8);
            *(uint4*)(smem + PB_B_OFF + off) =
                *(const uint4*)(g_zmt + (c0 + row) * N_NODES + k0 + ph * 128 + unit * 8);
        }
        __syncthreads();
        mma_tile_128(sb, wm, wn, lane, acc);
    }

    float* dst = g_covp[sp];
    int qr = lane >> 2, qc = (lane & 3) * 2;
#pragma unroll
    for (int mt = 0; mt < 4; mt++) {
#pragma unroll
        for (int nt = 0; nt < 4; nt++) {
            int r = r0 + wm + mt * 16 + qr;
            int c = c0 + wn + nt * 8 + qc;
            float v0 = acc[mt][nt][0], v1 = acc[mt][nt][1];
            float v2 = acc[mt][nt][2], v3 = acc[mt][nt][3];
            dst[r * F_DIM + c] = v0;
            dst[r * F_DIM + c + 1] = v1;
            dst[(r + 8) * F_DIM + c] = v2;
            dst[(r + 8) * F_DIM + c + 1] = v3;
            if (tid == 1) {
                dst[c * F_DIM + r] = v0;
                dst[(c + 1) * F_DIM + r] = v1;
                dst[c * F_DIM + r + 8] = v2;
                dst[(c + 1) * F_DIM + r + 8] = v3;
            }
        }
    }
}

// ---- cor: sum split partials inline; diag(a) broadcast via shared ----------
__global__ void cor_kernel() {
    int a = blockIdx.x, b = threadIdx.x;
    float cs = 0.f, db = 0.f;
#pragma unroll
    for (int s = 0; s < COV_SPLITS; s++) {
        cs += g_covp[s][a * F_DIM + b];
        db += g_covp[s][b * F_DIM + b];
    }
    __shared__ float sda;
    if (b == a) sda = cs;
    __syncthreads();
    float denom = sqrtf(sda) * sqrtf(db);
    float v = cs / denom;
    if (isnan(v)) v = 0.f;
    v = fminf(1.f, fmaxf(-1.f, v));
    if (a == b) v = 0.f;
    g_corb[a * F_DIM + b] = __float2bfloat16(v);
}

// ---- z2 = z + EPS * (w*zm) @ cor via HMMA ----------------------------------
__global__ void __launch_bounds__(256) z2_mma_kernel(const float* __restrict__ z) {
    extern __shared__ char smem[];
    uint32_t sb = smem_u32(smem);
    int t = threadIdx.x, wid = t >> 5, lane = t & 31;
    int r0 = blockIdx.x * 128, c0 = blockIdx.y * 128;
    int wm = (wid >> 2) * 64, wn = (wid & 3) * 32;
    float acc[4][4][4] = {};

    for (int ph = 0; ph < 2; ph++) {
        if (ph) __syncthreads();
        for (int q = t; q < 2048; q += 256) {
            int row = q >> 4, unit = q & 15;
            uint32_t off = (uint32_t)(row * 256 + ((unit ^ (row & 7)) << 4));
            *(uint4*)(smem + off) =
                *(const uint4*)(g_wzmb + (r0 + row) * F_DIM + ph * 128 + unit * 8);
            *(uint4*)(smem + PB_B_OFF + off) =
                *(const uint4*)(g_corb + (c0 + row) * F_DIM + ph * 128 + unit * 8);
        }
        __syncthreads();
        mma_tile_128(sb, wm, wn, lane, acc);
    }

    int qr = lane >> 2, qc = (lane & 3) * 2;
#pragma unroll
    for (int mt = 0; mt < 4; mt++) {
#pragma unroll
        for (int nt = 0; nt < 4; nt++) {
            int r = r0 + wm + mt * 16 + qr;
            int c = c0 + wn + nt * 8 + qc;
            float v0 = z[r * F_DIM + c] + 0.01f * acc[mt][nt][0];
            float v1 = z[r * F_DIM + c + 1] + 0.01f * acc[mt][nt][1];
            float v2 = z[(r + 8) * F_DIM + c] + 0.01f * acc[mt][nt][2];
            float v3 = z[(r + 8) * F_DIM + c + 1] + 0.01f * acc[mt][nt][3];
            *(__nv_bfloat162*)(g_zb + r * F_DIM + c) = __floats2bfloat162_rn(v0, v1);
            *(__nv_bfloat162*)(g_zb + (r + 8) * F_DIM + c) = __floats2bfloat162_rn(v2, v3);
        }
    }
}

// ---------------- per-node L2 norm ------------------------------------------
__global__ void norm_kernel() {
    int n = blockIdx.x;
    int t = threadIdx.x;                       // 64 threads
    uint4 v = ((const uint4*)(g_zb + n * F_DIM))[t];
    float s;
    {
        float2 f0 = __bfloat1622float2(*(__nv_bfloat162*)&v.x);
        float2 f1 = __bfloat1622float2(*(__nv_bfloat162*)&v.y);
        float2 f2 = __bfloat1622float2(*(__nv_bfloat162*)&v.z);
        float2 f3 = __bfloat1622float2(*(__nv_bfloat162*)&v.w);
        s = f0.x * f0.x + f0.y * f0.y + f1.x * f1.x + f1.y * f1.y
          + f2.x * f2.x + f2.y * f2.y + f3.x * f3.x + f3.y * f3.y;
    }
#pragma unroll
    for (int o = 16; o; o >>= 1) s += __shfl_down_sync(0xffffffffu, s, o);
    __shared__ float sw[2];
    if ((t & 31) == 0) sw[t >> 5] = s;
    __syncthreads();
    if (t == 0) g_nrm[n] = fmaxf(sqrtf(sw[0] + sw[1]), 1e-8f);
}

// ---------------- per-edge cosine -------------------------------------------
__global__ void edge_kernel() {
    int warp = (blockIdx.x * blockDim.x + threadIdx.x) >> 5;
    int lane = threadIdx.x & 31;
    if (warp >= E_EDGES) return;
    int i = g_ei[warp];
    int j = g_ei[E_EDGES + warp];
    uint4 a = ((const uint4*)(g_zb + i * F_DIM))[lane];
    uint4 b = ((const uint4*)(g_zb + j * F_DIM))[lane];
    float acc;
    {
        float2 a0 = __bfloat1622float2(*(__nv_bfloat162*)&a.x);
        float2 a1 = __bfloat1622float2(*(__nv_bfloat162*)&a.y);
        float2 a2 = __bfloat1622float2(*(__nv_bfloat162*)&a.z);
        float2 a3 = __bfloat1622float2(*(__nv_bfloat162*)&a.w);
        float2 b0 = __bfloat1622float2(*(__nv_bfloat162*)&b.x);
        float2 b1 = __bfloat1622float2(*(__nv_bfloat162*)&b.y);
        float2 b2 = __bfloat1622float2(*(__nv_bfloat162*)&b.z);
        float2 b3 = __bfloat1622float2(*(__nv_bfloat162*)&b.w);
        acc = a0.x * b0.x + a0.y * b0.y + a1.x * b1.x + a1.y * b1.y
            + a2.x * b2.x + a2.y * b2.y + a3.x * b3.x + a3.y * b3.y;
    }
#pragma unroll
    for (int o = 16; o; o >>= 1) acc += __shfl_down_sync(0xffffffffu, acc, o);
    if (lane == 0) {
        float sim = acc / (g_nrm[i] * g_nrm[j]);
        atomicAdd(&g_scores[i], sim);
        atomicAdd(&g_deg[i], 1.0f);
    }
}

// ---------------- penalty: 256x128 tiles, cp.async pipelined ----------------
__global__ void __launch_bounds__(256) penalty_mma_kernel() {
    extern __shared__ char smem[];
    uint32_t sb = smem_u32(smem);
    int t = threadIdx.x, wid = t >> 5, lane = t & 31;

    // decode linear index -> (rb, cb) with cb >= 2*rb; widths 64-2rb
    int rb = 0, cb;
    {
        int rem = blockIdx.x;
        int width = 64;
        while (rem >= width) { rem -= width; width -= 2; rb++; }
        cb = 2 * rb + rem;
    }
    int r0 = rb * 256, c0 = cb * 128;
    int wm = (wid >> 1) * 64, wn = (wid & 1) * 64;

    float acc[4][8][4] = {};

    // issue both stages' loads via cp.async
#pragma unroll
    for (int ph = 0; ph < 2; ph++) {
        uint32_t stage = ph * PN_STAGE;
        for (int q = t; q < 4096; q += 256) {           // A: 256 rows
            int row = q >> 4, unit = q & 15;
            uint32_t off = stage + (uint32_t)(row * 256 + ((unit ^ (row & 7)) << 4));
            cpa16(sb + off, g_zb + (r0 + row) * F_DIM + ph * 128 + unit * 8);
        }
        for (int q = t; q < 2048; q += 256) {           // B: 128 rows
            int row = q >> 4, unit = q & 15;
            uint32_t off = stage + PN_B_OFF +
                           (uint32_t)(row * 256 + ((unit ^ (row & 7)) << 4));
            cpa16(sb + off, g_zb + (c0 + row) * F_DIM + ph * 128 + unit * 8);
        }
        asm volatile("cp.async.commit_group;" ::: "memory");
    }

    asm volatile("cp.async.wait_group 1;" ::: "memory");
    __syncthreads();
    mma_tile_256(sb, sb + PN_B_OFF, wm, wn, lane, acc);
    asm volatile("cp.async.wait_group 0;" ::: "memory");
    __syncthreads();
    mma_tile_256(sb + PN_STAGE, sb + PN_STAGE + PN_B_OFF, wm, wn, lane, acc);

    // epilogue: per-element symmetric weight + adjacency + threshold
    float psum = 0.f;
    int qr = lane >> 2, qc = (lane & 3) * 2;
    int wbase = cb * 4 + (wn >> 5);
#pragma unroll
    for (int mt = 0; mt < 4; mt++) {
        int lr = wm + mt * 16 + qr;
        int gi0 = r0 + lr, gi1 = gi0 + 8;
        unsigned a00 = g_adj[gi0 * ADJ_ROW_WORDS + wbase];
        unsigned a01 = g_adj[gi0 * ADJ_ROW_WORDS + wbase + 1];
        unsigned a10 = g_adj[gi1 * ADJ_ROW_WORDS + wbase];
        unsigned a11 = g_adj[gi1 * ADJ_ROW_WORDS + wbase + 1];
#pragma unroll
        for (int nt = 0; nt < 8; nt++) {
            int bit = (nt & 3) * 8 + qc;
            unsigned w0 = (nt < 4) ? a00 : a01;
            unsigned w1 = (nt < 4) ? a10 : a11;
            int gj = c0 + wn + nt * 8 + qc;
            float v0 = acc[mt][nt][0], v1 = acc[mt][nt][1];
            float v2 = acc[mt][nt][2], v3 = acc[mt][nt][3];
            float wf00 = (gj > gi0) ? 2.f : ((gj == gi0) ? 1.f : 0.f);
            float wf01 = (gj + 1 > gi0) ? 2.f : ((gj + 1 == gi0) ? 1.f : 0.f);
            float wf10 = (gj > gi1) ? 2.f : ((gj == gi1) ? 1.f : 0.f);
            float wf11 = (gj + 1 > gi1) ? 2.f : ((gj + 1 == gi1) ? 1.f : 0.f);
            if (!((w0 >> bit) & 1u) && v0 > 0.8f) psum += v0 * wf00;
            if (!((w0 >> (bit + 1)) & 1u) && v1 > 0.8f) psum += v1 * wf01;
            if (!((w1 >> bit) & 1u) && v2 > 0.8f) psum += v2 * wf10;
            if (!((w1 >> (bit + 1)) & 1u) && v3 > 0.8f) psum += v3 * wf11;
        }
    }
#pragma unroll
    for (int o = 16; o; o >>= 1) psum += __shfl_down_sync(0xffffffffu, psum, o);
    __shared__ float red[8];
    if (lane == 0) red[wid] = psum;
    __syncthreads();
    if (t == 0) {
        float s = 0.f;
#pragma unroll
        for (int q = 0; q < 8; q++) s += red[q];
        atomicAdd(&g_penalty, (double)s);
    }
}

// ---------------- finalize --------------------------------------------------
__global__ void final_kernel(float* __restrict__ out) {
    int t = threadIdx.x;
    float acc = 0.f;
    for (int n = t; n < N_NODES; n += 256) {
        float d = g_deg[n];
        if (d == 0.f) d = 1.f;
        acc += g_scores[n] / d;
    }
#pragma unroll
    for (int o = 16; o; o >>= 1) acc += __shfl_down_sync(0xffffffffu, acc, o);
    __shared__ float red[8];
    if ((t & 31) == 0) red[t >> 5] = acc;
    __syncthreads();
    if (t == 0) {
        float tot = 0.f;
        for (int q = 0; q < 8; q++) tot += red[q];
        double hom = -(double)tot / (double)N_NODES;
        double pen = g_penalty / ((double)N_NODES * (double)N_NODES);
        out[0] = (float)(hom + pen);
    }
}

// ---------------- launch ----------------------------------------------------
extern "C" void kernel_launch(void* const* d_in, const int* in_sizes, int n_in,
                              void* d_out, int out_size) {
    const float* z       = (const float*)d_in[0];
    const void*  ei_raw  = d_in[2];
    const void*  k2u_raw = d_in[3];
    const void*  u2k_raw = d_in[4];
    float* out = (float*)d_out;

    static int smem_set = 0;
    if (!smem_set) {
        cudaFuncSetAttribute(penalty_mma_kernel,
            cudaFuncAttributeMaxDynamicSharedMemorySize, PN_TOTAL);
        cudaFuncSetAttribute(cov_mma_kernel,
            cudaFuncAttributeMaxDynamicSharedMemorySize, PB_TOTAL);
        cudaFuncSetAttribute(z2_mma_kernel,
            cudaFuncAttributeMaxDynamicSharedMemorySize, PB_TOTAL);
        smem_set = 1;
    }

    zero_kernel<<<4096, 256>>>();
    mean_conv_kernel<<<1280, 256>>>(z, ei_raw);
    prep2_kernel<<<128, 256>>>(z, ei_raw, k2u_raw, u2k_raw);
    cov_mma_kernel<<<dim3(3, COV_SPLITS), 256, PB_TOTAL>>>();
    cor_kernel<<<256, 256>>>();
    z2_mma_kernel<<<dim3(64, 2), 256, PB_TOTAL>>>(z);
    norm_kernel<<<N_NODES, 64>>>();
    edge_kernel<<<E_EDGES * 32 / 256, 256>>>();
    penalty_mma_kernel<<<PN_TILES, 256, PN_TOTAL>>>();
    final_kernel<<<1, 256>>>(out);
}

// round 15
// speedup vs baseline: 1.0412x; 1.0412x over previous
#include <cuda_runtime.h>
#include <cuda_bf16.h>
#include <cstdint>

#define N_NODES 8192
#define F_DIM   256
#define E_EDGES 262144
#define ADJ_ROW_WORDS (N_NODES / 32)              // 256
#define ADJ_WORDS     (N_NODES * ADJ_ROW_WORDS)   // 8MB
#define PB_B_OFF 32768
#define PB_TOTAL 65536
#define COV_SPLITS 16

// cov pipeline: 2 stages x (32KB A + 32KB B)
#define CV_STAGE 65536
#define CV_TOTAL (2 * CV_STAGE)                   // 128KB

// penalty: 256x128 tiles, upper-tri (cb >= 2*rb): 1056 tiles
#define PN_TILES 1056
#define PN_STAGE 98304                            // 64KB A + 32KB B
#define PN_B_OFF 65536
#define PN_TOTAL (2 * PN_STAGE)                   // 192KB

// ---------------- scratch ---------------------------------------------------
__device__ int           g_ei[2 * E_EDGES];
__device__ float         g_mean[F_DIM];                // raw column sums
__device__ float         g_covp[COV_SPLITS][F_DIM * F_DIM];  // split-K partials
__device__ __nv_bfloat16 g_corb[F_DIM * F_DIM];
__device__ __nv_bfloat16 g_zmt[F_DIM * N_NODES];       // zm^T bf16
__device__ __nv_bfloat16 g_wzmb[N_NODES * F_DIM];      // w*zm bf16
__device__ __nv_bfloat16 g_zb[N_NODES * F_DIM];        // z2 bf16
__device__ float         g_nrm[N_NODES];
__device__ unsigned      g_adj[ADJ_WORDS];
__device__ float         g_scores[N_NODES];
__device__ float         g_deg[N_NODES];
__device__ double        g_penalty;

__device__ __forceinline__ uint32_t smem_u32(const void* p) {
    uint32_t a;
    asm("{ .reg .u64 t; cvta.to.shared.u64 t, %1; cvt.u32.u64 %0, t; }"
        : "=r"(a) : "l"(p));
    return a;
}
__device__ __forceinline__ void cpa16(uint32_t saddr, const void* g) {
    asm volatile("cp.async.cg.shared.global [%0], [%1], 16;"
                 :: "r"(saddr), "l"(g));
}

// ---- HMMA inner loop for 128x128 tiles (cov / z2) ---------------------------
__device__ __forceinline__ void mma_tile_128(uint32_t sb, int wm, int wn,
                                             int lane, float acc[4][4][4]) {
#pragma unroll
    for (int ks = 0; ks < 128; ks += 16) {
        uint32_t a[4][4];
#pragma unroll
        for (int mt = 0; mt < 4; mt++) {
            int row = wm + mt * 16 + (lane & 15);
            int kc = ks + ((lane >> 4) << 3);
            uint32_t addr = sb + (uint32_t)(row * 256 +
                           ((((kc >> 3)) ^ (row & 7)) << 4));
            asm volatile(
                "ldmatrix.sync.aligned.m8n8.x4.shared.b16 {%0,%1,%2,%3}, [%4];"
                : "=r"(a[mt][0]), "=r"(a[mt][1]), "=r"(a[mt][2]), "=r"(a[mt][3])
                : "r"(addr));
        }
        uint32_t b[4][2];
#pragma unroll
        for (int pr = 0; pr < 2; pr++) {
            int row = wn + pr * 16 + ((lane >> 4) << 3) + (lane & 7);
            int kc = ks + (((lane >> 3) & 1) << 3);
            uint32_t addr = sb + PB_B_OFF + (uint32_t)(row * 256 +
                           ((((kc >> 3)) ^ (row & 7)) << 4));
            asm volatile(
                "ldmatrix.sync.aligned.m8n8.x4.shared.b16 {%0,%1,%2,%3}, [%4];"
                : "=r"(b[pr * 2][0]), "=r"(b[pr * 2][1]),
                  "=r"(b[pr * 2 + 1][0]), "=r"(b[pr * 2 + 1][1])
                : "r"(addr));
        }
#pragma unroll
        for (int mt = 0; mt < 4; mt++)
#pragma unroll
            for (int nt = 0; nt < 4; nt++)
                asm volatile(
                    "mma.sync.aligned.m16n8k16.row.col.f32.bf16.bf16.f32 "
                    "{%0,%1,%2,%3}, {%4,%5,%6,%7}, {%8,%9}, {%0,%1,%2,%3};"
                    : "+f"(acc[mt][nt][0]), "+f"(acc[mt][nt][1]),
                      "+f"(acc[mt][nt][2]), "+f"(acc[mt][nt][3])
                    : "r"(a[mt][0]), "r"(a[mt][1]), "r"(a[mt][2]), "r"(a[mt][3]),
                      "r"(b[nt][0]), "r"(b[nt][1]));
    }
}

// ---- HMMA inner loop for 256x128 tiles (penalty): warps 4(m) x 2(n) --------
__device__ __forceinline__ void mma_tile_256(uint32_t sbA, uint32_t sbB,
                                             int wm, int wn, int lane,
                                             float acc[4][8][4]) {
#pragma unroll
    for (int ks = 0; ks < 128; ks += 16) {
        uint32_t a[4][4];
#pragma unroll
        for (int mt = 0; mt < 4; mt++) {
            int row = wm + mt * 16 + (lane & 15);
            int kc = ks + ((lane >> 4) << 3);
            uint32_t addr = sbA + (uint32_t)(row * 256 +
                           ((((kc >> 3)) ^ (row & 7)) << 4));
            asm volatile(
                "ldmatrix.sync.aligned.m8n8.x4.shared.b16 {%0,%1,%2,%3}, [%4];"
                : "=r"(a[mt][0]), "=r"(a[mt][1]), "=r"(a[mt][2]), "=r"(a[mt][3])
                : "r"(addr));
        }
        uint32_t b[8][2];
#pragma unroll
        for (int pr = 0; pr < 4; pr++) {
            int row = wn + pr * 16 + ((lane >> 4) << 3) + (lane & 7);
            int kc = ks + (((lane >> 3) & 1) << 3);
            uint32_t addr = sbB + (uint32_t)(row * 256 +
                           ((((kc >> 3)) ^ (row & 7)) << 4));
            asm volatile(
                "ldmatrix.sync.aligned.m8n8.x4.shared.b16 {%0,%1,%2,%3}, [%4];"
                : "=r"(b[pr * 2][0]), "=r"(b[pr * 2][1]),
                  "=r"(b[pr * 2 + 1][0]), "=r"(b[pr * 2 + 1][1])
                : "r"(addr));
        }
#pragma unroll
        for (int mt = 0; mt < 4; mt++)
#pragma unroll
            for (int nt = 0; nt < 8; nt++)
                asm volatile(
                    "mma.sync.aligned.m16n8k16.row.col.f32.bf16.bf16.f32 "
                    "{%0,%1,%2,%3}, {%4,%5,%6,%7}, {%8,%9}, {%0,%1,%2,%3};"
                    : "+f"(acc[mt][nt][0]), "+f"(acc[mt][nt][1]),
                      "+f"(acc[mt][nt][2]), "+f"(acc[mt][nt][3])
                    : "r"(a[mt][0]), "r"(a[mt][1]), "r"(a[mt][2]), "r"(a[mt][3]),
                      "r"(b[nt][0]), "r"(b[nt][1]));
    }
}

// ---------------- zero scratch ----------------------------------------------
__global__ void zero_kernel() {
    int i = blockIdx.x * blockDim.x + threadIdx.x;
    int stride = gridDim.x * blockDim.x;
    for (int idx = i; idx < ADJ_WORDS; idx += stride) g_adj[idx] = 0u;
    if (i < F_DIM) g_mean[i] = 0.f;
    if (i < N_NODES) { g_scores[i] = 0.f; g_deg[i] = 0.f; }
    if (i == 0) g_penalty = 0.0;
}

// ---- grid-union: blocks 0-255 column sums; blocks 256-1279 edges+adjacency -
__global__ void mean_conv_kernel(const float* __restrict__ z,
                                 const void* __restrict__ ei_raw) {
    if (blockIdx.x < 256) {
        int f = threadIdx.x;
        int r0 = blockIdx.x * 32;
        float acc = 0.f;
        for (int r = 0; r < 32; r++) acc += z[(r0 + r) * F_DIM + f];
        atomicAdd(&g_mean[f], acc);
        return;
    }
    const long long* p = (const long long*)ei_raw;
    int bad = 0;
    if (threadIdx.x < 128) {
        long long v = p[threadIdx.x];
        bad = (v < 0 || v >= N_NODES) ? 1 : 0;
    }
    bad = __syncthreads_or(bad);               // 1 => data is int32
    int e = (blockIdx.x - 256) * blockDim.x + threadIdx.x;
    if (e >= E_EDGES) return;
    int i, j;
    if (bad) {
        i = ((const int*)ei_raw)[e];
        j = ((const int*)ei_raw)[E_EDGES + e];
    } else {
        i = (int)p[e];
        j = (int)p[E_EDGES + e];
    }
    i = min(max(i, 0), N_NODES - 1);
    j = min(max(j, 0), N_NODES - 1);
    g_ei[e] = i;
    g_ei[E_EDGES + e] = j;
    atomicOr(&g_adj[i * ADJ_ROW_WORDS + (j >> 5)], 1u << (j & 31));
    atomicOr(&g_adj[j * ADJ_ROW_WORDS + (i >> 5)], 1u << (i & 31));
}

// ---- build zm^T bf16 and w*zm bf16 (w + mean scaling folded in) ------------
__global__ void prep2_kernel(const float* __restrict__ z,
                             const void* __restrict__ ei_raw,
                             const void* __restrict__ k2u_raw,
                             const void* __restrict__ u2k_raw) {
    __shared__ __nv_bfloat16 S[64][258];
    __shared__ float Wv[64];
    __shared__ float Mv[256];
    int n0 = blockIdx.x * 64;
    int t = threadIdx.x;

    // dtype probe (per block, cheap: 128 L2-hit loads)
    const long long* p = (const long long*)ei_raw;
    int bad = 0;
    if (t < 128) {
        long long v = p[t];
        bad = (v < 0 || v >= N_NODES) ? 1 : 0;
    }
    bad = __syncthreads_or(bad);

    if (t < 64) {
        int n = n0 + t;
        float fa, fb;
        if (bad) {
            fa = (float)((const int*)k2u_raw)[n];
            fb = (float)((const int*)u2k_raw)[n];
        } else {
            fa = (float)((const long long*)k2u_raw)[n];
            fb = (float)((const long long*)u2k_raw)[n];
        }
        Wv[t] = __powf(0.9f, fa) + 1.f - __powf(0.9f, fb);
    }
    Mv[t] = g_mean[t] * (1.f / (float)N_NODES);
    __syncthreads();

    for (int idx = t; idx < 64 * 256; idx += 256) {
        int nl = idx >> 8, f = idx & 255;
        float zm = z[(n0 + nl) * F_DIM + f] - Mv[f];
        S[nl][f] = __float2bfloat16(zm);
        g_wzmb[(n0 + nl) * F_DIM + f] = __float2bfloat16(Wv[nl] * zm);
    }
    __syncthreads();
    for (int idx = t; idx < 256 * 64; idx += 256) {
        int f = idx >> 6, nl = idx & 63;
        g_zmt[f * N_NODES + n0 + nl] = S[nl][f];
    }
}

// ---- cov via HMMA: 3 tiles x 16 K-splits, cp.async 2-stage pipeline --------
__global__ void __launch_bounds__(256) cov_mma_kernel() {
    extern __shared__ char smem[];
    uint32_t sb = smem_u32(smem);
    int t = threadIdx.x, wid = t >> 5, lane = t & 31;
    int tid = blockIdx.x;                    // 0:(0,0) 1:(0,1) 2:(1,1)
    int sp  = blockIdx.y;                    // split index
    int fb1 = (tid == 2) ? 1 : 0;
    int fb2 = (tid == 0) ? 0 : 1;
    int r0 = fb1 * 128, c0 = fb2 * 128;
    int k0 = sp * (N_NODES / COV_SPLITS);    // 512 per split

    int wm = (wid >> 2) * 64, wn = (wid & 3) * 32;
    float acc[4][4][4] = {};

    // issue loads for phase ph into stage (ph&1)
    auto issue = [&](int ph) {
        uint32_t stage = (uint32_t)(ph & 1) * CV_STAGE;
        for (int q = t; q < 2048; q += 256) {
            int row = q >> 4, unit = q & 15;
            uint32_t off = stage + (uint32_t)(row * 256 + ((unit ^ (row & 7)) << 4));
            cpa16(sb + off,
                  g_zmt + (r0 + row) * N_NODES + k0 + ph * 128 + unit * 8);
            cpa16(sb + off + PB_B_OFF,
                  g_zmt + (c0 + row) * N_NODES + k0 + ph * 128 + unit * 8);
        }
        asm volatile("cp.async.commit_group;" ::: "memory");
    };

    issue(0);
    issue(1);

    asm volatile("cp.async.wait_group 1;" ::: "memory");
    __syncthreads();
    mma_tile_128(sb, wm, wn, lane, acc);
    __syncthreads();
    issue(2);

    asm volatile("cp.async.wait_group 1;" ::: "memory");
    __syncthreads();
    mma_tile_128(sb + CV_STAGE, wm, wn, lane, acc);
    __syncthreads();
    issue(3);

    asm volatile("cp.async.wait_group 1;" ::: "memory");
    __syncthreads();
    mma_tile_128(sb, wm, wn, lane, acc);

    asm volatile("cp.async.wait_group 0;" ::: "memory");
    __syncthreads();
    mma_tile_128(sb + CV_STAGE, wm, wn, lane, acc);

    float* dst = g_covp[sp];
    int qr = lane >> 2, qc = (lane & 3) * 2;
#pragma unroll
    for (int mt = 0; mt < 4; mt++) {
#pragma unroll
        for (int nt = 0; nt < 4; nt++) {
            int r = r0 + wm + mt * 16 + qr;
            int c = c0 + wn + nt * 8 + qc;
            float v0 = acc[mt][nt][0], v1 = acc[mt][nt][1];
            float v2 = acc[mt][nt][2], v3 = acc[mt][nt][3];
            dst[r * F_DIM + c] = v0;
            dst[r * F_DIM + c + 1] = v1;
            dst[(r + 8) * F_DIM + c] = v2;
            dst[(r + 8) * F_DIM + c + 1] = v3;
            if (tid == 1) {
                dst[c * F_DIM + r] = v0;
                dst[(c + 1) * F_DIM + r] = v1;
                dst[c * F_DIM + r + 8] = v2;
                dst[(c + 1) * F_DIM + r + 8] = v3;
            }
        }
    }
}

// ---- cor: sum split partials inline; diag(a) broadcast via shared ----------
__global__ void cor_kernel() {
    int a = blockIdx.x, b = threadIdx.x;
    float cs = 0.f, db = 0.f;
#pragma unroll
    for (int s = 0; s < COV_SPLITS; s++) {
        cs += g_covp[s][a * F_DIM + b];
        db += g_covp[s][b * F_DIM + b];
    }
    __shared__ float sda;
    if (b == a) sda = cs;
    __syncthreads();
    float denom = sqrtf(sda) * sqrtf(db);
    float v = cs / denom;
    if (isnan(v)) v = 0.f;
    v = fminf(1.f, fmaxf(-1.f, v));
    if (a == b) v = 0.f;
    g_corb[a * F_DIM + b] = __float2bfloat16(v);
}

// ---- z2 = z + EPS * (w*zm) @ cor via HMMA ----------------------------------
__global__ void __launch_bounds__(256) z2_mma_kernel(const float* __restrict__ z) {
    extern __shared__ char smem[];
    uint32_t sb = smem_u32(smem);
    int t = threadIdx.x, wid = t >> 5, lane = t & 31;
    int r0 = blockIdx.x * 128, c0 = blockIdx.y * 128;
    int wm = (wid >> 2) * 64, wn = (wid & 3) * 32;
    float acc[4][4][4] = {};

    for (int ph = 0; ph < 2; ph++) {
        if (ph) __syncthreads();
        for (int q = t; q < 2048; q += 256) {
            int row = q >> 4, unit = q & 15;
            uint32_t off = (uint32_t)(row * 256 + ((unit ^ (row & 7)) << 4));
            *(uint4*)(smem + off) =
                *(const uint4*)(g_wzmb + (r0 + row) * F_DIM + ph * 128 + unit * 8);
            *(uint4*)(smem + PB_B_OFF + off) =
                *(const uint4*)(g_corb + (c0 + row) * F_DIM + ph * 128 + unit * 8);
        }
        __syncthreads();
        mma_tile_128(sb, wm, wn, lane, acc);
    }

    int qr = lane >> 2, qc = (lane & 3) * 2;
#pragma unroll
    for (int mt = 0; mt < 4; mt++) {
#pragma unroll
        for (int nt = 0; nt < 4; nt++) {
            int r = r0 + wm + mt * 16 + qr;
            int c = c0 + wn + nt * 8 + qc;
            float v0 = z[r * F_DIM + c] + 0.01f * acc[mt][nt][0];
            float v1 = z[r * F_DIM + c + 1] + 0.01f * acc[mt][nt][1];
            float v2 = z[(r + 8) * F_DIM + c] + 0.01f * acc[mt][nt][2];
            float v3 = z[(r + 8) * F_DIM + c + 1] + 0.01f * acc[mt][nt][3];
            *(__nv_bfloat162*)(g_zb + r * F_DIM + c) = __floats2bfloat162_rn(v0, v1);
            *(__nv_bfloat162*)(g_zb + (r + 8) * F_DIM + c) = __floats2bfloat162_rn(v2, v3);
        }
    }
}

// ---------------- per-node L2 norm ------------------------------------------
__global__ void norm_kernel() {
    int n = blockIdx.x;
    int t = threadIdx.x;                       // 64 threads
    uint4 v = ((const uint4*)(g_zb + n * F_DIM))[t];
    float s;
    {
        float2 f0 = __bfloat1622float2(*(__nv_bfloat162*)&v.x);
        float2 f1 = __bfloat1622float2(*(__nv_bfloat162*)&v.y);
        float2 f2 = __bfloat1622float2(*(__nv_bfloat162*)&v.z);
        float2 f3 = __bfloat1622float2(*(__nv_bfloat162*)&v.w);
        s = f0.x * f0.x + f0.y * f0.y + f1.x * f1.x + f1.y * f1.y
          + f2.x * f2.x + f2.y * f2.y + f3.x * f3.x + f3.y * f3.y;
    }
#pragma unroll
    for (int o = 16; o; o >>= 1) s += __shfl_down_sync(0xffffffffu, s, o);
    __shared__ float sw[2];
    if ((t & 31) == 0) sw[t >> 5] = s;
    __syncthreads();
    if (t == 0) g_nrm[n] = fmaxf(sqrtf(sw[0] + sw[1]), 1e-8f);
}

// ---------------- per-edge cosine -------------------------------------------
__global__ void edge_kernel() {
    int warp = (blockIdx.x * blockDim.x + threadIdx.x) >> 5;
    int lane = threadIdx.x & 31;
    if (warp >= E_EDGES) return;
    int i = g_ei[warp];
    int j = g_ei[E_EDGES + warp];
    uint4 a = ((const uint4*)(g_zb + i * F_DIM))[lane];
    uint4 b = ((const uint4*)(g_zb + j * F_DIM))[lane];
    float acc;
    {
        float2 a0 = __bfloat1622float2(*(__nv_bfloat162*)&a.x);
        float2 a1 = __bfloat1622float2(*(__nv_bfloat162*)&a.y);
        float2 a2 = __bfloat1622float2(*(__nv_bfloat162*)&a.z);
        float2 a3 = __bfloat1622float2(*(__nv_bfloat162*)&a.w);
        float2 b0 = __bfloat1622float2(*(__nv_bfloat162*)&b.x);
        float2 b1 = __bfloat1622float2(*(__nv_bfloat162*)&b.y);
        float2 b2 = __bfloat1622float2(*(__nv_bfloat162*)&b.z);
        float2 b3 = __bfloat1622float2(*(__nv_bfloat162*)&b.w);
        acc = a0.x * b0.x + a0.y * b0.y + a1.x * b1.x + a1.y * b1.y
            + a2.x * b2.x + a2.y * b2.y + a3.x * b3.x + a3.y * b3.y;
    }
#pragma unroll
    for (int o = 16; o; o >>= 1) acc += __shfl_down_sync(0xffffffffu, acc, o);
    if (lane == 0) {
        float sim = acc / (g_nrm[i] * g_nrm[j]);
        atomicAdd(&g_scores[i], sim);
        atomicAdd(&g_deg[i], 1.0f);
    }
}

// ---------------- penalty: 256x128 tiles, cp.async pipelined ----------------
__global__ void __launch_bounds__(256) penalty_mma_kernel() {
    extern __shared__ char smem[];
    uint32_t sb = smem_u32(smem);
    int t = threadIdx.x, wid = t >> 5, lane = t & 31;

    // decode linear index -> (rb, cb) with cb >= 2*rb; widths 64-2rb
    int rb = 0, cb;
    {
        int rem = blockIdx.x;
        int width = 64;
        while (rem >= width) { rem -= width; width -= 2; rb++; }
        cb = 2 * rb + rem;
    }
    int r0 = rb * 256, c0 = cb * 128;
    int wm = (wid >> 1) * 64, wn = (wid & 1) * 64;

    float acc[4][8][4] = {};

    // issue both stages' loads via cp.async
#pragma unroll
    for (int ph = 0; ph < 2; ph++) {
        uint32_t stage = ph * PN_STAGE;
        for (int q = t; q < 4096; q += 256) {           // A: 256 rows
            int row = q >> 4, unit = q & 15;
            uint32_t off = stage + (uint32_t)(row * 256 + ((unit ^ (row & 7)) << 4));
            cpa16(sb + off, g_zb + (r0 + row) * F_DIM + ph * 128 + unit * 8);
        }
        for (int q = t; q < 2048; q += 256) {           // B: 128 rows
            int row = q >> 4, unit = q & 15;
            uint32_t off = stage + PN_B_OFF +
                           (uint32_t)(row * 256 + ((unit ^ (row & 7)) << 4));
            cpa16(sb + off, g_zb + (c0 + row) * F_DIM + ph * 128 + unit * 8);
        }
        asm volatile("cp.async.commit_group;" ::: "memory");
    }

    asm volatile("cp.async.wait_group 1;" ::: "memory");
    __syncthreads();
    mma_tile_256(sb, sb + PN_B_OFF, wm, wn, lane, acc);
    asm volatile("cp.async.wait_group 0;" ::: "memory");
    __syncthreads();
    mma_tile_256(sb + PN_STAGE, sb + PN_STAGE + PN_B_OFF, wm, wn, lane, acc);

    // epilogue: per-element symmetric weight + adjacency + threshold
    float psum = 0.f;
    int qr = lane >> 2, qc = (lane & 3) * 2;
    int wbase = cb * 4 + (wn >> 5);
#pragma unroll
    for (int mt = 0; mt < 4; mt++) {
        int lr = wm + mt * 16 + qr;
        int gi0 = r0 + lr, gi1 = gi0 + 8;
        unsigned a00 = g_adj[gi0 * ADJ_ROW_WORDS + wbase];
        unsigned a01 = g_adj[gi0 * ADJ_ROW_WORDS + wbase + 1];
        unsigned a10 = g_adj[gi1 * ADJ_ROW_WORDS + wbase];
        unsigned a11 = g_adj[gi1 * ADJ_ROW_WORDS + wbase + 1];
#pragma unroll
        for (int nt = 0; nt < 8; nt++) {
            int bit = (nt & 3) * 8 + qc;
            unsigned w0 = (nt < 4) ? a00 : a01;
            unsigned w1 = (nt < 4) ? a10 : a11;
            int gj = c0 + wn + nt * 8 + qc;
            float v0 = acc[mt][nt][0], v1 = acc[mt][nt][1];
            float v2 = acc[mt][nt][2], v3 = acc[mt][nt][3];
            float wf00 = (gj > gi0) ? 2.f : ((gj == gi0) ? 1.f : 0.f);
            float wf01 = (gj + 1 > gi0) ? 2.f : ((gj + 1 == gi0) ? 1.f : 0.f);
            float wf10 = (gj > gi1) ? 2.f : ((gj == gi1) ? 1.f : 0.f);
            float wf11 = (gj + 1 > gi1) ? 2.f : ((gj + 1 == gi1) ? 1.f : 0.f);
            if (!((w0 >> bit) & 1u) && v0 > 0.8f) psum += v0 * wf00;
            if (!((w0 >> (bit + 1)) & 1u) && v1 > 0.8f) psum += v1 * wf01;
            if (!((w1 >> bit) & 1u) && v2 > 0.8f) psum += v2 * wf10;
            if (!((w1 >> (bit + 1)) & 1u) && v3 > 0.8f) psum += v3 * wf11;
        }
    }
#pragma unroll
    for (int o = 16; o; o >>= 1) psum += __shfl_down_sync(0xffffffffu, psum, o);
    __shared__ float red[8];
    if (lane == 0) red[wid] = psum;
    __syncthreads();
    if (t == 0) {
        float s = 0.f;
#pragma unroll
        for (int q = 0; q < 8; q++) s += red[q];
        atomicAdd(&g_penalty, (double)s);
    }
}

// ---------------- finalize --------------------------------------------------
__global__ void final_kernel(float* __restrict__ out) {
    int t = threadIdx.x;
    float acc = 0.f;
    for (int n = t; n < N_NODES; n += 256) {
        float d = g_deg[n];
        if (d == 0.f) d = 1.f;
        acc += g_scores[n] / d;
    }
#pragma unroll
    for (int o = 16; o; o >>= 1) acc += __shfl_down_sync(0xffffffffu, acc, o);
    __shared__ float red[8];
    if ((t & 31) == 0) red[t >> 5] = acc;
    __syncthreads();
    if (t == 0) {
        float tot = 0.f;
        for (int q = 0; q < 8; q++) tot += red[q];
        double hom = -(double)tot / (double)N_NODES;
        double pen = g_penalty / ((double)N_NODES * (double)N_NODES);
        out[0] = (float)(hom + pen);
    }
}

// ---------------- launch ----------------------------------------------------
extern "C" void kernel_launch(void* const* d_in, const int* in_sizes, int n_in,
                              void* d_out, int out_size) {
    const float* z       = (const float*)d_in[0];
    const void*  ei_raw  = d_in[2];
    const void*  k2u_raw = d_in[3];
    const void*  u2k_raw = d_in[4];
    float* out = (float*)d_out;

    static int smem_set = 0;
    if (!smem_set) {
        cudaFuncSetAttribute(penalty_mma_kernel,
            cudaFuncAttributeMaxDynamicSharedMemorySize, PN_TOTAL);
        cudaFuncSetAttribute(cov_mma_kernel,
            cudaFuncAttributeMaxDynamicSharedMemorySize, CV_TOTAL);
        cudaFuncSetAttribute(z2_mma_kernel,
            cudaFuncAttributeMaxDynamicSharedMemorySize, PB_TOTAL);
        smem_set = 1;
    }

    zero_kernel<<<4096, 256>>>();
    mean_conv_kernel<<<1280, 256>>>(z, ei_raw);
    prep2_kernel<<<128, 256>>>(z, ei_raw, k2u_raw, u2k_raw);
    cov_mma_kernel<<<dim3(3, COV_SPLITS), 256, CV_TOTAL>>>();
    cor_kernel<<<256, 256>>>();
    z2_mma_kernel<<<dim3(64, 2), 256, PB_TOTAL>>>(z);
    norm_kernel<<<N_NODES, 64>>>();
    edge_kernel<<<E_EDGES * 32 / 256, 256>>>();
    penalty_mma_kernel<<<PN_TILES, 256, PN_TOTAL>>>();
    final_kernel<<<1, 256>>>(out);
}